// round 1
// baseline (speedup 1.0000x reference)
#include <cuda_runtime.h>
#include <cuda_bf16.h>
#include <cstdint>

// Integration_4123168604342
// x: (T=128, B=4, E=10000, F=16) f32, dummy_index: int scalar
// out: (128, 4, 10000, 15) f32 = tanh(cumsum_T(f * dt))
//
// One 16-lane group per (b,e) series. Lane i owns input channel i.
// Group loads 16 consecutive floats per t (64B; 2 groups/warp = 128B coalesced).
// dt channel broadcast via shfl within the 16-lane segment.

#define T_DIM   128
#define B_DIM   4
#define E_DIM   10000
#define F_DIM   16
#define FO_DIM  15
#define BE_DIM  (B_DIM * E_DIM)           // 40000 groups
#define STRIDE_T   ((size_t)BE_DIM * F_DIM)   // 640000 floats per t (input)
#define STRIDE_TO  ((size_t)BE_DIM * FO_DIM)  // 600000 floats per t (output)

__device__ __forceinline__ float tanh_fast(float x) {
    float y;
    asm("tanh.approx.f32 %0, %1;" : "=f"(y) : "f"(x));
    return y;
}

__global__ __launch_bounds__(256)
void integration_kernel(const float* __restrict__ x,
                        const int* __restrict__ didx,
                        float* __restrict__ out) {
    const int gid   = blockIdx.x * blockDim.x + threadIdx.x;
    const int group = gid >> 4;       // (b,e) flat index
    const int lane  = gid & 15;       // channel
    if (group >= BE_DIM) return;

    const int d = *didx;              // dummy (time) channel
    const bool is_t = (lane == d);
    const int oc = lane - (lane > d ? 1 : 0);   // output channel for non-t lanes

    const float* __restrict__ xp = x + (size_t)group * F_DIM + lane;
    float* __restrict__ op = out + (size_t)group * FO_DIM + oc;

    // Preload t=0 and t=1 rows (dt0 = t[0] + t[1]).
    float v0 = xp[0];
    float v1 = xp[STRIDE_T];
    const float t0 = __shfl_sync(0xFFFFFFFFu, v0, d, 16);
    const float t1 = __shfl_sync(0xFFFFFFFFu, v1, d, 16);

    // t = 0
    float acc = v0 * (t0 + t1);
    if (!is_t) op[0] = tanh_fast(acc);
    float prev_t = t0;

    // t = 1 .. 127, with one-iteration load prefetch for MLP.
    float v = v1;
    #pragma unroll 4
    for (int t = 1; t < T_DIM; ++t) {
        float vnext = 0.0f;
        if (t + 1 < T_DIM) vnext = xp[(size_t)(t + 1) * STRIDE_T];
        const float tc = __shfl_sync(0xFFFFFFFFu, v, d, 16);
        acc = fmaf(v, tc - prev_t, acc);
        if (!is_t) op[(size_t)t * STRIDE_TO] = tanh_fast(acc);
        prev_t = tc;
        v = vnext;
    }
}

extern "C" void kernel_launch(void* const* d_in, const int* in_sizes, int n_in,
                              void* d_out, int out_size) {
    const float* x   = (const float*)d_in[0];
    const int* didx  = (const int*)d_in[1];
    float* out       = (float*)d_out;

    const int total_threads = BE_DIM * 16;        // 640000
    const int block = 256;
    const int grid = (total_threads + block - 1) / block;  // 2500
    integration_kernel<<<grid, block>>>(x, didx, out);
}

// round 2
// speedup vs baseline: 1.2342x; 1.2342x over previous
#include <cuda_runtime.h>
#include <cuda_bf16.h>
#include <cstdint>

// Integration_4123168604342
// x: (T=128, B=4, E=10000, F=16) f32, dummy_index: int scalar
// out: (128, 4, 10000, 15) f32 = tanh(cumsum_T(f * dt))
//
// One 16-lane group per (b,e) series; lane i owns channel i.
// R2: explicit 4-deep load pipeline (front-batched LDGs, MLP_p1=4) to fill
// the ~18KB/SM in-flight-bytes requirement for DRAM saturation.

#define T_DIM   128
#define B_DIM   4
#define E_DIM   10000
#define F_DIM   16
#define FO_DIM  15
#define BE_DIM  (B_DIM * E_DIM)               // 40000 groups
#define STRIDE_T   ((size_t)BE_DIM * F_DIM)   // 640000 floats per t (input)
#define STRIDE_TO  ((size_t)BE_DIM * FO_DIM)  // 600000 floats per t (output)

__device__ __forceinline__ float tanh_fast(float x) {
    float y;
    asm("tanh.approx.f32 %0, %1;" : "=f"(y) : "f"(x));
    return y;
}

__global__ __launch_bounds__(256)
void integration_kernel(const float* __restrict__ x,
                        const int* __restrict__ didx,
                        float* __restrict__ out) {
    const int gid   = blockIdx.x * blockDim.x + threadIdx.x;
    const int group = gid >> 4;       // (b,e) flat index
    const int lane  = gid & 15;       // channel
    if (group >= BE_DIM) return;

    const int d = *didx;              // dummy (time) channel
    const bool is_t = (lane == d);
    const int oc = lane - (lane > d ? 1 : 0);   // output channel for non-t lanes

    const float* __restrict__ xp = x + (size_t)group * F_DIM + lane;
    float* __restrict__ op = out + (size_t)group * FO_DIM + oc;

    // ---- prologue: rows 0..3 in flight together ----
    float b0 = xp[0];
    float b1 = xp[STRIDE_T];
    float b2 = xp[2 * STRIDE_T];
    float b3 = xp[3 * STRIDE_T];

    const float t0 = __shfl_sync(0xFFFFFFFFu, b0, d, 16);
    const float t1 = __shfl_sync(0xFFFFFFFFu, b1, d, 16);

    // t = 0: dt0 = t[0] + t[1]
    float acc = b0 * (t0 + t1);
    if (!is_t) op[0] = tanh_fast(acc);
    float prev_t = t0;

    // ---- steady state: process rows base..base+3, prefetch base+4..base+7 ----
    // base = 0 skips row 0 (already done).
    #pragma unroll 1
    for (int base = 0; base < T_DIM - 4; base += 4) {
        // front-batched, unguarded prefetch of the next 4 rows (MLP_p1 = 4)
        const float* p = xp + (size_t)(base + 4) * STRIDE_T;
        float n0 = p[0];
        float n1 = p[STRIDE_T];
        float n2 = p[2 * STRIDE_T];
        float n3 = p[3 * STRIDE_T];

        if (base > 0) {
            const float tc = __shfl_sync(0xFFFFFFFFu, b0, d, 16);
            acc = fmaf(b0, tc - prev_t, acc);
            if (!is_t) op[(size_t)base * STRIDE_TO] = tanh_fast(acc);
            prev_t = tc;
        }
        {
            const float tc = __shfl_sync(0xFFFFFFFFu, b1, d, 16);
            acc = fmaf(b1, tc - prev_t, acc);
            if (!is_t) op[(size_t)(base + 1) * STRIDE_TO] = tanh_fast(acc);
            prev_t = tc;
        }
        {
            const float tc = __shfl_sync(0xFFFFFFFFu, b2, d, 16);
            acc = fmaf(b2, tc - prev_t, acc);
            if (!is_t) op[(size_t)(base + 2) * STRIDE_TO] = tanh_fast(acc);
            prev_t = tc;
        }
        {
            const float tc = __shfl_sync(0xFFFFFFFFu, b3, d, 16);
            acc = fmaf(b3, tc - prev_t, acc);
            if (!is_t) op[(size_t)(base + 3) * STRIDE_TO] = tanh_fast(acc);
            prev_t = tc;
        }
        b0 = n0; b1 = n1; b2 = n2; b3 = n3;
    }

    // ---- epilogue: rows 124..127 ----
    {
        const int base = T_DIM - 4;
        const float tcA = __shfl_sync(0xFFFFFFFFu, b0, d, 16);
        acc = fmaf(b0, tcA - prev_t, acc);
        if (!is_t) op[(size_t)base * STRIDE_TO] = tanh_fast(acc);

        const float tcB = __shfl_sync(0xFFFFFFFFu, b1, d, 16);
        acc = fmaf(b1, tcB - tcA, acc);
        if (!is_t) op[(size_t)(base + 1) * STRIDE_TO] = tanh_fast(acc);

        const float tcC = __shfl_sync(0xFFFFFFFFu, b2, d, 16);
        acc = fmaf(b2, tcC - tcB, acc);
        if (!is_t) op[(size_t)(base + 2) * STRIDE_TO] = tanh_fast(acc);

        const float tcD = __shfl_sync(0xFFFFFFFFu, b3, d, 16);
        acc = fmaf(b3, tcD - tcC, acc);
        if (!is_t) op[(size_t)(base + 3) * STRIDE_TO] = tanh_fast(acc);
    }
}

extern "C" void kernel_launch(void* const* d_in, const int* in_sizes, int n_in,
                              void* d_out, int out_size) {
    const float* x   = (const float*)d_in[0];
    const int* didx  = (const int*)d_in[1];
    float* out       = (float*)d_out;

    const int total_threads = BE_DIM * 16;        // 640000
    const int block = 256;
    const int grid = (total_threads + block - 1) / block;  // 2500
    integration_kernel<<<grid, block>>>(x, didx, out);
}